// round 1
// baseline (speedup 1.0000x reference)
#include <cuda_runtime.h>
#include <math.h>

#define H 1024
#define NC 3
#define B 128
#define T 128
#define G3 (3*H)   // 3072

// ---------------- scratch (device globals; no allocation allowed) ----------------
__device__ float g_gx[(size_t)B*T*G3];   // 192 MB: gates_x [b*T+t, 3H]; reused as Wy [t*B+b, H]
__device__ float g_op[(size_t)T*B*H];    // 64 MB: premise GRU outputs, layout [t][b][h]
__device__ float g_hA[B*H];
__device__ float g_hB[B*H];
__device__ float g_gh[B*G3];
__device__ float g_wh[B*H];
__device__ float g_sc[B*T];
__device__ float g_al[B*T];
__device__ float g_r[B*H];
__device__ float g_tmp[B*H];

// ---------------- big GEMM: C[M,N] = A[M,K] @ B (+bias). BM=BN=128, BK=8, 256 thr, 8x8 microtile
// TRANSB: B is [N,K] row-major (C = A @ B^T). else B is [K,N] row-major.
template<bool TRANSB, bool ACCUM, bool BIAS>
__global__ void gemm128(const float* __restrict__ A, const float* __restrict__ Bm,
                        const float* __restrict__ bias, float* __restrict__ Cm,
                        int M, int N, int K)
{
    __shared__ float As[8][128];
    __shared__ float Bs[8][128];
    int tid = threadIdx.x;
    int bm = blockIdx.y * 128;
    int bn = blockIdx.x * 128;
    int trow = (tid / 16) * 8;
    int tcol = (tid % 16) * 8;
    float acc[8][8] = {};

    int a_row = tid >> 1;
    int a_k4  = (tid & 1) * 4;

    for (int k0 = 0; k0 < K; k0 += 8) {
        float4 av = *(const float4*)&A[(size_t)(bm + a_row)*K + k0 + a_k4];
        As[a_k4+0][a_row] = av.x;
        As[a_k4+1][a_row] = av.y;
        As[a_k4+2][a_row] = av.z;
        As[a_k4+3][a_row] = av.w;
        if (TRANSB) {
            int n  = tid >> 1;
            int k4 = (tid & 1) * 4;
            float4 bv = *(const float4*)&Bm[(size_t)(bn + n)*K + k0 + k4];
            Bs[k4+0][n] = bv.x; Bs[k4+1][n] = bv.y;
            Bs[k4+2][n] = bv.z; Bs[k4+3][n] = bv.w;
        } else {
            int kr = tid >> 5;
            int n4 = (tid & 31) * 4;
            float4 bv = *(const float4*)&Bm[(size_t)(k0 + kr)*N + bn + n4];
            *(float4*)&Bs[kr][n4] = bv;
        }
        __syncthreads();
        #pragma unroll
        for (int k = 0; k < 8; k++) {
            float a_frag[8], b_frag[8];
            #pragma unroll
            for (int i = 0; i < 8; i++) a_frag[i] = As[k][trow + i];
            #pragma unroll
            for (int j = 0; j < 8; j++) b_frag[j] = Bs[k][tcol + j];
            #pragma unroll
            for (int i = 0; i < 8; i++)
                #pragma unroll
                for (int j = 0; j < 8; j++)
                    acc[i][j] += a_frag[i] * b_frag[j];
        }
        __syncthreads();
    }

    #pragma unroll
    for (int i = 0; i < 8; i++) {
        size_t row = (size_t)(bm + trow + i);
        #pragma unroll
        for (int j = 0; j < 8; j += 4) {
            int col = bn + tcol + j;
            float4 v = { acc[i][j], acc[i][j+1], acc[i][j+2], acc[i][j+3] };
            if (BIAS) { v.x += bias[col]; v.y += bias[col+1]; v.z += bias[col+2]; v.w += bias[col+3]; }
            if (ACCUM) {
                float4 o = *(const float4*)&Cm[row*N + col];
                v.x += o.x; v.y += o.y; v.z += o.z; v.w += o.w;
            }
            *(float4*)&Cm[row*N + col] = v;
        }
    }
}

// ---------------- small-M GEMM: M must be 128. BM=128, BN=32, BK=16, 128 thr, 8x4 microtile
template<bool TRANSB, bool ACCUM, bool BIAS>
__global__ void gemm_smallM(const float* __restrict__ A, const float* __restrict__ Bm,
                            const float* __restrict__ bias, float* __restrict__ Cm,
                            int N, int K)
{
    __shared__ float As[16][128];
    __shared__ float Bs[16][32];
    int tid = threadIdx.x;
    int bn = blockIdx.x * 32;
    int ty = tid >> 3;          // 0..15
    int tx = tid & 7;           // 0..7
    int trow = ty * 8, tcol = tx * 4;
    float acc[8][4] = {};

    for (int k0 = 0; k0 < K; k0 += 16) {
        #pragma unroll
        for (int l = 0; l < 4; l++) {
            int idx = tid + l * 128;       // 0..511 float4 slots
            int row = idx >> 2;
            int k4  = (idx & 3) * 4;
            float4 av = *(const float4*)&A[(size_t)row*K + k0 + k4];
            As[k4+0][row] = av.x; As[k4+1][row] = av.y;
            As[k4+2][row] = av.z; As[k4+3][row] = av.w;
        }
        if (TRANSB) {
            int n  = tid >> 2;            // 0..31
            int k4 = (tid & 3) * 4;
            float4 bv = *(const float4*)&Bm[(size_t)(bn + n)*K + k0 + k4];
            Bs[k4+0][n] = bv.x; Bs[k4+1][n] = bv.y;
            Bs[k4+2][n] = bv.z; Bs[k4+3][n] = bv.w;
        } else {
            int kr = tid >> 3;            // 0..15
            int n4 = (tid & 7) * 4;
            float4 bv = *(const float4*)&Bm[(size_t)(k0 + kr)*N + bn + n4];
            *(float4*)&Bs[kr][n4] = bv;
        }
        __syncthreads();
        #pragma unroll
        for (int k = 0; k < 16; k++) {
            float b0 = Bs[k][tcol], b1 = Bs[k][tcol+1], b2 = Bs[k][tcol+2], b3 = Bs[k][tcol+3];
            #pragma unroll
            for (int i = 0; i < 8; i++) {
                float a = As[k][trow + i];
                acc[i][0] += a*b0; acc[i][1] += a*b1; acc[i][2] += a*b2; acc[i][3] += a*b3;
            }
        }
        __syncthreads();
    }

    #pragma unroll
    for (int i = 0; i < 8; i++) {
        size_t row = (size_t)(trow + i);
        int col = bn + tcol;
        float4 v = { acc[i][0], acc[i][1], acc[i][2], acc[i][3] };
        if (BIAS) { v.x += bias[col]; v.y += bias[col+1]; v.z += bias[col+2]; v.w += bias[col+3]; }
        if (ACCUM) {
            float4 o = *(const float4*)&Cm[row*N + col];
            v.x += o.x; v.y += o.y; v.z += o.z; v.w += o.w;
        }
        *(float4*)&Cm[row*N + col] = v;
    }
}

// ---------------- GRU gate fusion: h_new from gx[t], gh, h_prev ----------------
__global__ void gru_gate(const float* __restrict__ gx,   // [B*T, 3H]
                         const float* __restrict__ gh,   // [B, 3H]
                         const float* __restrict__ hprev,
                         float* __restrict__ hnext,
                         float* __restrict__ o_t,        // o_p slot [B,H] or nullptr
                         int t)
{
    int idx = blockIdx.x * blockDim.x + threadIdx.x;   // 0..B*H-1
    int b = idx >> 10;
    int j = idx & 1023;
    const float* gxr = gx + (size_t)(b*T + t) * G3;
    const float* ghr = gh + (size_t)b * G3;
    float xr = gxr[j], xz = gxr[j + H], xn = gxr[j + 2*H];
    float hr = ghr[j], hz = ghr[j + H], hn = ghr[j + 2*H];
    float r = 1.f / (1.f + expf(-(xr + hr)));
    float z = 1.f / (1.f + expf(-(xz + hz)));
    float n = tanhf(xn + r * hn);
    float hnew = (1.f - z) * n + z * hprev[idx];
    hnext[idx] = hnew;
    if (o_t) o_t[(size_t)b*H + j] = hnew;
}

// ---------------- attention scores: sc[b,t] = sum_h tanh(wy[p,h]+wh[b,h])*wa[h], p=t*B+b
__global__ void scores_kernel(const float* __restrict__ wy, const float* __restrict__ wh,
                              const float* __restrict__ wa, float* __restrict__ sc)
{
    int warp = threadIdx.x >> 5, lane = threadIdx.x & 31;
    int p = blockIdx.x * 4 + warp;    // p = t*B + b
    int t = p >> 7, b = p & 127;
    const float* wyr = wy + (size_t)p * H;
    const float* whr = wh + (size_t)b * H;
    float acc = 0.f;
    for (int h = lane; h < H; h += 32)
        acc += tanhf(wyr[h] + whr[h]) * wa[h];
    #pragma unroll
    for (int o = 16; o > 0; o >>= 1) acc += __shfl_xor_sync(0xffffffff, acc, o);
    if (lane == 0) sc[b*T + t] = acc;
}

__global__ void softmax_kernel(const float* __restrict__ sc, float* __restrict__ al)
{
    __shared__ float s[128];
    int b = blockIdx.x, t = threadIdx.x;
    float v = sc[b*T + t];
    s[t] = v; __syncthreads();
    for (int o = 64; o > 0; o >>= 1) { if (t < o) s[t] = fmaxf(s[t], s[t + o]); __syncthreads(); }
    float mx = s[0]; __syncthreads();
    float e = expf(v - mx);
    s[t] = e; __syncthreads();
    for (int o = 64; o > 0; o >>= 1) { if (t < o) s[t] += s[t + o]; __syncthreads(); }
    al[b*T + t] = e / s[0];
}

// r[b,h] = sum_t alpha[b,t] * o_p[t,b,h]
__global__ void rweight_kernel(const float* __restrict__ al, const float* __restrict__ op,
                               float* __restrict__ r)
{
    int idx = blockIdx.x * blockDim.x + threadIdx.x;
    int b = idx >> 10, j = idx & 1023;
    float acc = 0.f;
    #pragma unroll 4
    for (int t = 0; t < T; t++)
        acc += al[b*T + t] * op[(size_t)t*B*H + (size_t)b*H + j];
    r[idx] = acc;
}

// logits + log_softmax: tmp holds pre-tanh h_star
__global__ void out_kernel(const float* __restrict__ tmp, const float* __restrict__ ow,
                           const float* __restrict__ ob, float* __restrict__ out)
{
    __shared__ float s0[128], s1[128], s2[128];
    int b = blockIdx.x, tid = threadIdx.x;
    float p0 = 0.f, p1 = 0.f, p2 = 0.f;
    for (int h = tid; h < H; h += 128) {
        float hs = tanhf(tmp[(size_t)b*H + h]);
        p0 += hs * ow[0*H + h];
        p1 += hs * ow[1*H + h];
        p2 += hs * ow[2*H + h];
    }
    s0[tid] = p0; s1[tid] = p1; s2[tid] = p2; __syncthreads();
    for (int o = 64; o > 0; o >>= 1) {
        if (tid < o) { s0[tid] += s0[tid+o]; s1[tid] += s1[tid+o]; s2[tid] += s2[tid+o]; }
        __syncthreads();
    }
    if (tid == 0) {
        float l0 = tanhf(s0[0] + ob[0]);
        float l1 = tanhf(s1[0] + ob[1]);
        float l2 = tanhf(s2[0] + ob[2]);
        float mx = fmaxf(l0, fmaxf(l1, l2));
        float e0 = expf(l0 - mx), e1 = expf(l1 - mx), e2 = expf(l2 - mx);
        float lse = mx + logf(e0 + e1 + e2);
        out[b*3 + 0] = l0 - lse;
        out[b*3 + 1] = l1 - lse;
        out[b*3 + 2] = l2 - lse;
    }
}

// ---------------- launch ----------------
extern "C" void kernel_launch(void* const* d_in, const int* in_sizes, int n_in,
                              void* d_out, int out_size)
{
    const float* premise    = (const float*)d_in[0];
    const float* hypothesis = (const float*)d_in[1];
    const float* p_Wih = (const float*)d_in[2];
    const float* p_Whh = (const float*)d_in[3];
    const float* p_bih = (const float*)d_in[4];
    const float* p_bhh = (const float*)d_in[5];
    const float* h_Wih = (const float*)d_in[6];
    const float* h_Whh = (const float*)d_in[7];
    const float* h_bih = (const float*)d_in[8];
    const float* h_bhh = (const float*)d_in[9];
    const float* W_y     = (const float*)d_in[10];
    const float* W_h     = (const float*)d_in[11];
    const float* W_alpha = (const float*)d_in[12];
    const float* W_x     = (const float*)d_in[13];
    const float* W_p     = (const float*)d_in[14];
    const float* out_w   = (const float*)d_in[15];
    const float* out_b   = (const float*)d_in[16];
    float* out = (float*)d_out;

    float *gx, *op, *hA, *hB, *gh, *wh, *sc, *al, *rr, *tmp;
    cudaGetSymbolAddress((void**)&gx,  g_gx);
    cudaGetSymbolAddress((void**)&op,  g_op);
    cudaGetSymbolAddress((void**)&hA,  g_hA);
    cudaGetSymbolAddress((void**)&hB,  g_hB);
    cudaGetSymbolAddress((void**)&gh,  g_gh);
    cudaGetSymbolAddress((void**)&wh,  g_wh);
    cudaGetSymbolAddress((void**)&sc,  g_sc);
    cudaGetSymbolAddress((void**)&al,  g_al);
    cudaGetSymbolAddress((void**)&rr,  g_r);
    cudaGetSymbolAddress((void**)&tmp, g_tmp);

    cudaMemsetAsync(hA, 0, (size_t)B*H*sizeof(float));

    // gates_x premise: gx[b*T+t, 3H] = premise @ p_Wih^T + p_bih
    gemm128<true,false,true><<<dim3(G3/128, (B*T)/128), 256>>>(premise, p_Wih, p_bih, gx, B*T, G3, H);

    float* hc = hA; float* hn = hB;
    for (int t = 0; t < T; t++) {
        gemm_smallM<true,false,true><<<G3/32, 128>>>(hc, p_Whh, p_bhh, gh, G3, H);
        gru_gate<<<(B*H)/256, 256>>>(gx, gh, hc, hn, op + (size_t)t*B*H, t);
        float* tswap = hc; hc = hn; hn = tswap;
    }

    // gates_x hypothesis (reuse gx buffer)
    gemm128<true,false,true><<<dim3(G3/128, (B*T)/128), 256>>>(hypothesis, h_Wih, h_bih, gx, B*T, G3, H);

    for (int t = 0; t < T; t++) {
        gemm_smallM<true,false,true><<<G3/32, 128>>>(hc, h_Whh, h_bhh, gh, G3, H);
        gru_gate<<<(B*H)/256, 256>>>(gx, gh, hc, hn, nullptr, t);
        float* tswap = hc; hc = hn; hn = tswap;
    }
    // hc == h_final == o_h[-1]

    // Wy[t*B+b, H] = o_p @ W_y  (reuse gx buffer as Wy)
    float* wy = gx;
    gemm128<false,false,false><<<dim3(H/128, (T*B)/128), 256>>>(op, W_y, nullptr, wy, T*B, H, H);
    // Wh = h_final @ W_h
    gemm_smallM<false,false,false><<<H/32, 128>>>(hc, W_h, nullptr, wh, H, H);

    scores_kernel<<<(T*B)/4, 128>>>(wy, wh, W_alpha, sc);
    softmax_kernel<<<B, 128>>>(sc, al);
    rweight_kernel<<<(B*H)/256, 256>>>(al, op, rr);

    // h_star pre-activation: tmp = r @ W_p + h_final @ W_x
    gemm_smallM<false,false,false><<<H/32, 128>>>(rr, W_p, nullptr, tmp, H, H);
    gemm_smallM<false,true ,false><<<H/32, 128>>>(hc, W_x, nullptr, tmp, H, H);

    out_kernel<<<B, 128>>>(tmp, out_w, out_b, out);
}